// round 14
// baseline (speedup 1.0000x reference)
#include <cuda_runtime.h>
#include <cuda_fp16.h>
#include <cstdint>

#define NW    8192
#define CL    16
#define CHID  128
#define GATES 512
#define CDIM  64
#define WDIM  300
#define ODIM  512
#define KREAL 556

// ---------------- device scratch ----------------
__device__ __align__(16) __half g_P16[2 * 128 * GATES];  // preproj fp16 [dir][ch][n=4j+ty], bias folded
__device__ __align__(16) __half g_B[2][GATES * CHID];    // Whh fp16, row-permuted + XOR8 swizzle
__device__ __align__(16) __half g_Wh[9 * 512 * 64];      // W_out fp16, 9 chunks, swizzled
__device__ __align__(16) float  g_cf[NW * 256];

// ---------------- helpers ----------------
__device__ __forceinline__ uint32_t smem_u32(const void* p) {
    uint32_t a;
    asm("{ .reg .u64 t; cvta.to.shared.u64 t, %1; cvt.u32.u64 %0, t; }" : "=r"(a) : "l"(p));
    return a;
}
__device__ __forceinline__ float tanh_m(float x) {
    float y;
    asm("tanh.approx.f32 %0, %1;" : "=f"(y) : "f"(x));
    return y;
}
__device__ __forceinline__ float sig_m(float x) {
    return fmaf(0.5f, tanh_m(0.5f * x), 0.5f);
}
__device__ __forceinline__ float tanhf_fast(float x) {
    return 2.0f * __fdividef(1.0f, 1.0f + __expf(-2.0f * x)) - 1.0f;
}
__device__ __forceinline__ void ldm4(uint32_t* r, uint32_t addr) {
    asm volatile("ldmatrix.sync.aligned.m8n8.x4.shared.b16 {%0,%1,%2,%3}, [%4];"
                 : "=r"(r[0]), "=r"(r[1]), "=r"(r[2]), "=r"(r[3]) : "r"(addr));
}
__device__ __forceinline__ void mma16816(float* d, const uint32_t* a, uint32_t b0, uint32_t b1) {
    asm volatile("mma.sync.aligned.m16n8k16.row.col.f32.f16.f16.f32 "
                 "{%0,%1,%2,%3}, {%4,%5,%6,%7}, {%8,%9}, {%0,%1,%2,%3};"
                 : "+f"(d[0]), "+f"(d[1]), "+f"(d[2]), "+f"(d[3])
                 : "r"(a[0]), "r"(a[1]), "r"(a[2]), "r"(a[3]), "r"(b0), "r"(b1));
}
__device__ __forceinline__ void bar_half(int id) {
    asm volatile("bar.sync %0, 256;" :: "r"(id) : "memory");
}
__device__ __forceinline__ void cp16(uint32_t dst, const void* src) {
    asm volatile("cp.async.cg.shared.global [%0], [%1], 16;" :: "r"(dst), "l"(src) : "memory");
}
__device__ __forceinline__ void cp_commit() {
    asm volatile("cp.async.commit_group;" ::: "memory");
}
__device__ __forceinline__ void cp_wait0() {
    asm volatile("cp.async.wait_group 0;" ::: "memory");
}
__device__ __forceinline__ void lds128(uint32_t* q, uint32_t addr) {
    asm volatile("ld.shared.v4.b32 {%0,%1,%2,%3}, [%4];"
                 : "=r"(q[0]), "=r"(q[1]), "=r"(q[2]), "=r"(q[3]) : "r"(addr));
}

// ---------------- combined prep kernel ----------------
// blocks [0,256): P16 table (4-lane reduce); [256,288): Whh fp16; [288,360): W_out fp16
__global__ void prep_all(const float* __restrict__ ct,
                         const float* __restrict__ Wf, const float* __restrict__ bif,
                         const float* __restrict__ bhf,
                         const float* __restrict__ Wb, const float* __restrict__ bib,
                         const float* __restrict__ bhb,
                         const float* __restrict__ Whh_f, const float* __restrict__ Whh_b,
                         const float* __restrict__ W_out) {
    const int b = blockIdx.x, tid = threadIdx.x;
    __shared__ float cs[CDIM];
    if (b < 256) {
        const int dir = b >> 7, ch = b & 127;
        const int g = tid >> 2, q = tid & 3;
        const float* W  = dir ? Wb : Wf;
        const float* bi = dir ? bib : bif;
        const float* bh = dir ? bhb : bhf;
        if (tid < CDIM) cs[tid] = ct[ch * CDIM + tid];
        __syncthreads();
        const float4* cc4 = (const float4*)&cs[q * 16];
        const float4 c0 = cc4[0], c1 = cc4[1], c2 = cc4[2], c3 = cc4[3];
#pragma unroll
        for (int p = 0; p < 4; ++p) {
            const int n = p * 128 + g;
            const int j = n >> 2, ty = n & 3, r = ty * CHID + j;
            const float4* wr = (const float4*)&W[r * CDIM + q * 16];
            const float4 w0 = wr[0], w1 = wr[1], w2 = wr[2], w3 = wr[3];
            float s = w0.x * c0.x + w0.y * c0.y + w0.z * c0.z + w0.w * c0.w;
            s += w1.x * c1.x + w1.y * c1.y + w1.z * c1.z + w1.w * c1.w;
            s += w2.x * c2.x + w2.y * c2.y + w2.z * c2.z + w2.w * c2.w;
            s += w3.x * c3.x + w3.y * c3.y + w3.z * c3.z + w3.w * c3.w;
            s += __shfl_xor_sync(0xFFFFFFFFu, s, 1);
            s += __shfl_xor_sync(0xFFFFFFFFu, s, 2);
            if (q == 0)
                g_P16[(((dir << 7) + ch) << 9) + n] = __float2half(s + bi[r] + bh[r]);
        }
    } else if (b < 288) {
        const int cid = (b - 256) * 512 + tid;        // 16384
        const int dir = cid >> 13;
        const int rem = cid & 8191;
        const int rr = rem >> 4, cs_w = rem & 15;
        const int chunk = cs_w ^ (rr & 7);
        const int k0 = chunk * 8;
        const int j = ((rr >> 6) << 4) | (rr & 15);
        const int ty = (rr >> 4) & 3;
        const int r0 = ty * CHID + j;
        const float* W = dir ? Whh_b : Whh_f;
        const float4 f0 = *(const float4*)&W[r0 * CHID + k0];
        const float4 f1 = *(const float4*)&W[r0 * CHID + k0 + 4];
        __half2 h0 = __floats2half2_rn(f0.x, f0.y), h1 = __floats2half2_rn(f0.z, f0.w);
        __half2 h2 = __floats2half2_rn(f1.x, f1.y), h3 = __floats2half2_rn(f1.z, f1.w);
        uint4 u;
        u.x = *(uint32_t*)&h0; u.y = *(uint32_t*)&h1;
        u.z = *(uint32_t*)&h2; u.w = *(uint32_t*)&h3;
        *(uint4*)((char*)g_B[dir] + rr * 256 + cs_w * 16) = u;
    } else {
        const int cid = (b - 288) * 512 + tid;        // 36864
        const int kc = cid / 4096;
        const int rem = cid & 4095;
        const int n = rem >> 3, cs_w = rem & 7;
        const int chunk = cs_w ^ (n & 7);
        const int k0 = chunk * 8;
        float f[8];
#pragma unroll
        for (int i = 0; i < 8; ++i) {
            const int kk = kc * 64 + k0 + i;
            f[i] = (kk < KREAL) ? W_out[n * KREAL + kk] : 0.0f;
        }
        uint4 uh;
        __half2 p0 = __floats2half2_rn(f[0], f[1]), p1 = __floats2half2_rn(f[2], f[3]);
        __half2 p2 = __floats2half2_rn(f[4], f[5]), p3 = __floats2half2_rn(f[6], f[7]);
        uh.x = *(uint32_t*)&p0; uh.y = *(uint32_t*)&p1;
        uh.z = *(uint32_t*)&p2; uh.w = *(uint32_t*)&p3;
        *(uint4*)((char*)g_Wh + (uint32_t)(kc * 65536 + n * 128 + cs_w * 16)) = uh;
    }
}

// ---------------- HMMA bidirectional char-LSTM ----------------
// P(t) read at step TOP into accumulators (latency hidden under MMA issue);
// P(t+1) prefetch issued after bar#1, overlapping the epilogue.
#define CI_OFF 0
#define A_OFF  4096
#define B_OFF  20480
#define P_OFF  151552
#define P_STRIDE 1072
#define LSTM_SMEM (P_OFF + 64 * P_STRIDE)   // 220160

__global__ __launch_bounds__(512, 1) void lstm_kernel(const int* __restrict__ char_ids) {
    extern __shared__ char smem[];
    const uint32_t sb = smem_u32(smem);
    int* ci_s = (int*)(smem + CI_OFF);

    const int tid = threadIdx.x, wid = tid >> 5, lane = tid & 31;
    const int dir = blockIdx.y;
    const int w_base = blockIdx.x * 64;
    const int wm = wid >> 3, wj = wid & 7;

    {
        const int* src = char_ids + (size_t)w_base * CL;
        ci_s[tid] = src[tid];
        ci_s[tid + 512] = src[tid + 512];
        float4* az = (float4*)(smem + A_OFF);
        az[tid] = make_float4(0.f, 0.f, 0.f, 0.f);
        az[tid + 512] = make_float4(0.f, 0.f, 0.f, 0.f);
        const float4* bsrc = (const float4*)g_B[dir];
        float4* bdst = (float4*)(smem + B_OFF);
#pragma unroll
        for (int i = 0; i < 16; ++i) bdst[tid + i * 512] = bsrc[tid + i * 512];
    }
    __syncthreads();

    const int pw = tid >> 3;
    const int pc0 = tid & 7;
    const uint32_t pdst0 = sb + P_OFF + pw * P_STRIDE;
    const char* psrc_dir = (const char*)g_P16 + ((size_t)dir << 17);

    // prologue: stage P(t0), publish before first top-read
    {
        const int t0 = dir ? (CL - 1) : 0;
        const int ch = ci_s[pw * CL + t0];
        const char* srow = psrc_dir + ((size_t)ch << 10);
#pragma unroll
        for (int i = 0; i < 8; ++i) {
            const int c = pc0 + i * 8;
            cp16(pdst0 + c * 16, srow + c * 16);
        }
        cp_commit();
    }
    cp_wait0();
    __syncthreads();

    const int asub = lane >> 3;
    const int arow0 = wm * 32 + ((asub & 1) << 3) + (lane & 7);
    const int acp = asub >> 1;
    const int arm = arow0 & 7;
    const uint32_t a_base = sb + A_OFF + arow0 * 256;

    const int brow0 = wj * 64 + ((lane >> 4) << 3) + (lane & 7);
    const int bcp = (lane >> 3) & 1;
    const int brm = brow0 & 7;
    const uint32_t b_base = sb + B_OFF + brow0 * 256;

    const int mybar = 1 + wm;

    float d[2][8][4];
    float c_st[16], hs_st[16];
#pragma unroll
    for (int u = 0; u < 16; ++u) { c_st[u] = 0.f; hs_st[u] = 0.f; }

#pragma unroll 1
    for (int ti = 0; ti < CL; ++ti) {
        const int t = dir ? (CL - 1 - ti) : ti;

        // top: init accumulators from P(t) (smem; latency hidden under MMA issue)
#pragma unroll
        for (int mt = 0; mt < 2; ++mt)
#pragma unroll
            for (int rw = 0; rw < 2; ++rw) {
                const int wordl = wm * 32 + mt * 16 + (lane >> 2) + rw * 8;
#pragma unroll
                for (int jh = 0; jh < 2; ++jh) {
                    const int jg0 = wj * 16 + jh * 8 + 2 * (lane & 3);
                    uint32_t q[4];
                    lds128(q, sb + P_OFF + wordl * P_STRIDE + jg0 * 8);
#pragma unroll
                    for (int rj = 0; rj < 2; ++rj) {
                        const float2 pa = __half22float2(*(__half2*)&q[rj * 2 + 0]);
                        const float2 pb = __half22float2(*(__half2*)&q[rj * 2 + 1]);
                        const int r = rw * 2 + rj;
                        d[mt][0 + jh][r] = pa.x;
                        d[mt][2 + jh][r] = pa.y;
                        d[mt][4 + jh][r] = pb.x;
                        d[mt][6 + jh][r] = pb.y;
                    }
                }
            }

        // gates = P(t) + h(t-1) @ Whh^T
#pragma unroll
        for (int ks = 0; ks < 8; ++ks) {
            uint32_t A0[4], A1[4];
            ldm4(A0, a_base + (((ks * 2 + acp) ^ arm) << 4));
            ldm4(A1, a_base + 16 * 256 + (((ks * 2 + acp) ^ arm) << 4));
#pragma unroll
            for (int nb = 0; nb < 4; ++nb) {
                uint32_t B[4];
                ldm4(B, b_base + nb * 16 * 256 + (((ks * 2 + bcp) ^ brm) << 4));
                mma16816(d[0][nb * 2 + 0], A0, B[0], B[1]);
                mma16816(d[0][nb * 2 + 1], A0, B[2], B[3]);
                mma16816(d[1][nb * 2 + 0], A1, B[0], B[1]);
                mma16816(d[1][nb * 2 + 1], A1, B[2], B[3]);
            }
        }

        bar_half(mybar);   // A reads + P(t) reads complete (half-wide)

        // issue P(t+1) prefetch now -> overlaps epilogue compute
        if (ti + 1 < CL) {
            const int tn = dir ? (t - 1) : (t + 1);
            const int ch = ci_s[pw * CL + tn];
            const char* srow = psrc_dir + ((size_t)ch << 10);
#pragma unroll
            for (int i = 0; i < 8; ++i) {
                const int c = pc0 + i * 8;
                cp16(pdst0 + c * 16, srow + c * 16);
            }
            cp_commit();
        }

        // epilogue: activations, c update, h sum, h(t) -> A
#pragma unroll
        for (int mt = 0; mt < 2; ++mt) {
#pragma unroll
            for (int rw = 0; rw < 2; ++rw) {
                const int wordl = wm * 32 + mt * 16 + (lane >> 2) + rw * 8;
#pragma unroll
                for (int jh = 0; jh < 2; ++jh) {
                    float hv[2];
#pragma unroll
                    for (int rj = 0; rj < 2; ++rj) {
                        const int r = rw * 2 + rj;
                        const float gi = d[mt][0 + jh][r];
                        const float gf = d[mt][2 + jh][r];
                        const float gg = d[mt][4 + jh][r];
                        const float go = d[mt][6 + jh][r];
                        const int u = ((mt * 2 + rw) * 2 + jh) * 2 + rj;
                        const float cc = sig_m(gf) * c_st[u] + sig_m(gi) * tanh_m(gg);
                        c_st[u] = cc;
                        const float hh = sig_m(go) * tanh_m(cc);
                        hs_st[u] += hh;
                        hv[rj] = hh;
                    }
                    const int kk0 = wj * 16 + jh * 8 + 2 * (lane & 3);
                    const int chunk = kk0 >> 3;
                    const uint32_t off =
                        (uint32_t)(wordl * 256 + ((chunk ^ (wordl & 7)) << 4) + (kk0 & 7) * 2);
                    *(__half2*)(smem + A_OFF + off) = __floats2half2_rn(hv[0], hv[1]);
                }
            }
        }
        cp_wait0();        // own P(t+1) chunks landed
        bar_half(mybar);   // h(t) + all half's P(t+1) published
    }

#pragma unroll
    for (int mt = 0; mt < 2; ++mt)
#pragma unroll
        for (int rw = 0; rw < 2; ++rw) {
            const int wordl = wm * 32 + mt * 16 + (lane >> 2) + rw * 8;
#pragma unroll
            for (int jh = 0; jh < 2; ++jh)
#pragma unroll
                for (int rj = 0; rj < 2; ++rj) {
                    const int jg = wj * 16 + jh * 8 + 2 * (lane & 3) + rj;
                    const int u = ((mt * 2 + rw) * 2 + jh) * 2 + rj;
                    g_cf[(size_t)(w_base + wordl) * 256 + dir * 128 + jg] = hs_st[u];
                }
        }
}

// ---------------- tensor-core output GEMM (single-pass fp16) ----------------
#define OG_WID 0
#define OG_AH  1024
#define OG_WH  9216
#define OG_SMEM (OG_WH + 65536)   // 74752

__global__ __launch_bounds__(512, 1) void outgemm_kernel(const int* __restrict__ word_ids,
                                                         const float* __restrict__ word_table,
                                                         const float* __restrict__ b_out,
                                                         float* __restrict__ out) {
    extern __shared__ char smem[];
    const uint32_t sb = smem_u32(smem);
    int* wid_s = (int*)(smem + OG_WID);

    const int tid = threadIdx.x, wid = tid >> 5, lane = tid & 31;
    const int w_base = blockIdx.x * 64;
    const int wm = wid >> 3, wn = wid & 7;

    if (tid < 64) wid_s[tid] = word_ids[w_base + tid];
    __syncthreads();

    const int asub = lane >> 3;
    const int arow0 = wm * 32 + ((asub & 1) << 3) + (lane & 7);
    const int acp = asub >> 1;
    const int arm = arow0 & 7;
    const uint32_t ah_base = sb + OG_AH + arow0 * 128;

    const int brow0 = wn * 64 + ((lane >> 4) << 3) + (lane & 7);
    const int bcp = (lane >> 3) & 1;
    const int brm = brow0 & 7;
    const uint32_t bh_base = sb + OG_WH + brow0 * 128;

    float d[2][8][4];
#pragma unroll
    for (int mt = 0; mt < 2; ++mt)
#pragma unroll
        for (int nt = 0; nt < 8; ++nt)
#pragma unroll
            for (int r = 0; r < 4; ++r) d[mt][nt][r] = 0.f;

    const int sm = tid >> 3;
    const int sk0 = (tid & 7) * 8;
    const int swid = wid_s[sm];
    const uint32_t soff = (uint32_t)(sm * 128 + (((sk0 >> 3) ^ (sm & 7)) << 4));

#pragma unroll 1
    for (int kc = 0; kc < 9; ++kc) {
        __syncthreads();
        // W via cp.async first (hidden behind feat gather/convert)
        {
            const char* srch = (const char*)g_Wh + kc * 65536;
#pragma unroll
            for (int i = 0; i < 8; ++i) {
                const uint32_t bo = (uint32_t)(tid + i * 512) * 16;
                cp16(sb + OG_WH + bo, srch + bo);
            }
            cp_commit();
        }
        // feat gather + fp16 convert
        {
            float f[8];
#pragma unroll
            for (int i = 0; i < 8; ++i) {
                const int kk = kc * 64 + sk0 + i;
                float v;
                if (kk < WDIM) v = word_table[(size_t)swid * WDIM + kk];
                else if (kk < KREAL) v = g_cf[(size_t)(w_base + sm) * 256 + (kk - WDIM)];
                else v = 0.0f;
                f[i] = v;
            }
            uint4 uh;
            __half2 p0 = __floats2half2_rn(f[0], f[1]), p1 = __floats2half2_rn(f[2], f[3]);
            __half2 p2 = __floats2half2_rn(f[4], f[5]), p3 = __floats2half2_rn(f[6], f[7]);
            uh.x = *(uint32_t*)&p0; uh.y = *(uint32_t*)&p1;
            uh.z = *(uint32_t*)&p2; uh.w = *(uint32_t*)&p3;
            *(uint4*)(smem + OG_AH + soff) = uh;
        }
        cp_wait0();
        __syncthreads();
        // MMA: Ah * Wh
#pragma unroll
        for (int ks = 0; ks < 4; ++ks) {
            const uint32_t aoff = (uint32_t)(((ks * 2 + acp) ^ arm) << 4);
            const uint32_t boff = (uint32_t)(((ks * 2 + bcp) ^ brm) << 4);
            uint32_t Ah0[4], Ah1[4];
            ldm4(Ah0, ah_base + aoff);
            ldm4(Ah1, ah_base + 16 * 128 + aoff);
#pragma unroll
            for (int nb = 0; nb < 4; ++nb) {
                uint32_t Bh[4];
                ldm4(Bh, bh_base + nb * 16 * 128 + boff);
                mma16816(d[0][nb * 2 + 0], Ah0, Bh[0], Bh[1]);
                mma16816(d[0][nb * 2 + 1], Ah0, Bh[2], Bh[3]);
                mma16816(d[1][nb * 2 + 0], Ah1, Bh[0], Bh[1]);
                mma16816(d[1][nb * 2 + 1], Ah1, Bh[2], Bh[3]);
            }
        }
    }

#pragma unroll
    for (int mt = 0; mt < 2; ++mt)
#pragma unroll
        for (int rw = 0; rw < 2; ++rw) {
            const int wordl = wm * 32 + mt * 16 + (lane >> 2) + rw * 8;
            const size_t row = (size_t)(w_base + wordl) * ODIM;
#pragma unroll
            for (int nt = 0; nt < 8; ++nt) {
                const int n0 = wn * 64 + nt * 8 + 2 * (lane & 3);
                float2 r;
                r.x = tanhf_fast(d[mt][nt][rw * 2 + 0] + b_out[n0]);
                r.y = tanhf_fast(d[mt][nt][rw * 2 + 1] + b_out[n0 + 1]);
                *(float2*)&out[row + n0] = r;
            }
        }
}

// ---------------- launch ----------------
extern "C" void kernel_launch(void* const* d_in, const int* in_sizes, int n_in,
                              void* d_out, int out_size) {
    const int* word_ids     = (const int*)d_in[0];
    const int* char_ids     = (const int*)d_in[1];
    const float* word_table = (const float*)d_in[2];
    const float* char_table = (const float*)d_in[3];
    const float* Wih_f = (const float*)d_in[4];
    const float* Whh_f = (const float*)d_in[5];
    const float* bih_f = (const float*)d_in[6];
    const float* bhh_f = (const float*)d_in[7];
    const float* Wih_b = (const float*)d_in[8];
    const float* Whh_b = (const float*)d_in[9];
    const float* bih_b = (const float*)d_in[10];
    const float* bhh_b = (const float*)d_in[11];
    const float* W_out = (const float*)d_in[12];
    const float* b_out = (const float*)d_in[13];
    float* out = (float*)d_out;

    cudaFuncSetAttribute(lstm_kernel, cudaFuncAttributeMaxDynamicSharedMemorySize, LSTM_SMEM);
    cudaFuncSetAttribute(outgemm_kernel, cudaFuncAttributeMaxDynamicSharedMemorySize, OG_SMEM);

    prep_all<<<360, 512>>>(char_table, Wih_f, bih_f, bhh_f, Wih_b, bih_b, bhh_b,
                           Whh_f, Whh_b, W_out);
    lstm_kernel<<<dim3(128, 2), 512, LSTM_SMEM>>>(char_ids);
    outgemm_kernel<<<128, 512, OG_SMEM>>>(word_ids, word_table, b_out, out);
}

// round 17
// speedup vs baseline: 1.0863x; 1.0863x over previous
#include <cuda_runtime.h>
#include <cuda_fp16.h>
#include <cstdint>

#define NW    8192
#define CL    16
#define CHID  128
#define GATES 512
#define CDIM  64
#define WDIM  300
#define ODIM  512
#define KREAL 556

// ---------------- device scratch ----------------
__device__ __align__(16) __half g_P16[2 * 128 * GATES];  // preproj fp16 [dir][ch][n=4j+ty], bias folded
__device__ __align__(16) __half g_B[2][GATES * CHID];    // Whh fp16, row-permuted + XOR8 swizzle
__device__ __align__(16) __half g_Wh[9 * 512 * 64];      // W_out fp16, 9 chunks, swizzled
__device__ __align__(16) float  g_cf[NW * 256];

// ---------------- helpers ----------------
__device__ __forceinline__ uint32_t smem_u32(const void* p) {
    uint32_t a;
    asm("{ .reg .u64 t; cvta.to.shared.u64 t, %1; cvt.u32.u64 %0, t; }" : "=r"(a) : "l"(p));
    return a;
}
__device__ __forceinline__ float tanh_m(float x) {
    float y;
    asm("tanh.approx.f32 %0, %1;" : "=f"(y) : "f"(x));
    return y;
}
__device__ __forceinline__ float sig_m(float x) {
    return fmaf(0.5f, tanh_m(0.5f * x), 0.5f);
}
__device__ __forceinline__ float tanhf_fast(float x) {
    return 2.0f * __fdividef(1.0f, 1.0f + __expf(-2.0f * x)) - 1.0f;
}
__device__ __forceinline__ void ldm4(uint32_t* r, uint32_t addr) {
    asm volatile("ldmatrix.sync.aligned.m8n8.x4.shared.b16 {%0,%1,%2,%3}, [%4];"
                 : "=r"(r[0]), "=r"(r[1]), "=r"(r[2]), "=r"(r[3]) : "r"(addr));
}
__device__ __forceinline__ void mma16816(float* d, const uint32_t* a, uint32_t b0, uint32_t b1) {
    asm volatile("mma.sync.aligned.m16n8k16.row.col.f32.f16.f16.f32 "
                 "{%0,%1,%2,%3}, {%4,%5,%6,%7}, {%8,%9}, {%0,%1,%2,%3};"
                 : "+f"(d[0]), "+f"(d[1]), "+f"(d[2]), "+f"(d[3])
                 : "r"(a[0]), "r"(a[1]), "r"(a[2]), "r"(a[3]), "r"(b0), "r"(b1));
}
__device__ __forceinline__ void bar_half(int id) {
    asm volatile("bar.sync %0, 256;" :: "r"(id) : "memory");
}
__device__ __forceinline__ void cp16(uint32_t dst, const void* src) {
    asm volatile("cp.async.cg.shared.global [%0], [%1], 16;" :: "r"(dst), "l"(src) : "memory");
}
__device__ __forceinline__ void cp_commit() {
    asm volatile("cp.async.commit_group;" ::: "memory");
}
__device__ __forceinline__ void cp_wait0() {
    asm volatile("cp.async.wait_group 0;" ::: "memory");
}
__device__ __forceinline__ void lds128(uint32_t* q, uint32_t addr) {
    asm volatile("ld.shared.v4.b32 {%0,%1,%2,%3}, [%4];"
                 : "=r"(q[0]), "=r"(q[1]), "=r"(q[2]), "=r"(q[3]) : "r"(addr));
}

// ---------------- combined prep kernel ----------------
// blocks [0,256): P16 table (4-lane reduce); [256,288): Whh fp16; [288,360): W_out fp16
__global__ void prep_all(const float* __restrict__ ct,
                         const float* __restrict__ Wf, const float* __restrict__ bif,
                         const float* __restrict__ bhf,
                         const float* __restrict__ Wb, const float* __restrict__ bib,
                         const float* __restrict__ bhb,
                         const float* __restrict__ Whh_f, const float* __restrict__ Whh_b,
                         const float* __restrict__ W_out) {
    const int b = blockIdx.x, tid = threadIdx.x;
    __shared__ float cs[CDIM];
    if (b < 256) {
        const int dir = b >> 7, ch = b & 127;
        const int g = tid >> 2, q = tid & 3;
        const float* W  = dir ? Wb : Wf;
        const float* bi = dir ? bib : bif;
        const float* bh = dir ? bhb : bhf;
        if (tid < CDIM) cs[tid] = ct[ch * CDIM + tid];
        __syncthreads();
        const float4* cc4 = (const float4*)&cs[q * 16];
        const float4 c0 = cc4[0], c1 = cc4[1], c2 = cc4[2], c3 = cc4[3];
#pragma unroll
        for (int p = 0; p < 4; ++p) {
            const int n = p * 128 + g;
            const int j = n >> 2, ty = n & 3, r = ty * CHID + j;
            const float4* wr = (const float4*)&W[r * CDIM + q * 16];
            const float4 w0 = wr[0], w1 = wr[1], w2 = wr[2], w3 = wr[3];
            float s = w0.x * c0.x + w0.y * c0.y + w0.z * c0.z + w0.w * c0.w;
            s += w1.x * c1.x + w1.y * c1.y + w1.z * c1.z + w1.w * c1.w;
            s += w2.x * c2.x + w2.y * c2.y + w2.z * c2.z + w2.w * c2.w;
            s += w3.x * c3.x + w3.y * c3.y + w3.z * c3.z + w3.w * c3.w;
            s += __shfl_xor_sync(0xFFFFFFFFu, s, 1);
            s += __shfl_xor_sync(0xFFFFFFFFu, s, 2);
            if (q == 0)
                g_P16[(((dir << 7) + ch) << 9) + n] = __float2half(s + bi[r] + bh[r]);
        }
    } else if (b < 288) {
        const int cid = (b - 256) * 512 + tid;        // 16384
        const int dir = cid >> 13;
        const int rem = cid & 8191;
        const int rr = rem >> 4, cs_w = rem & 15;
        const int chunk = cs_w ^ (rr & 7);
        const int k0 = chunk * 8;
        const int j = ((rr >> 6) << 4) | (rr & 15);
        const int ty = (rr >> 4) & 3;
        const int r0 = ty * CHID + j;
        const float* W = dir ? Whh_b : Whh_f;
        const float4 f0 = *(const float4*)&W[r0 * CHID + k0];
        const float4 f1 = *(const float4*)&W[r0 * CHID + k0 + 4];
        __half2 h0 = __floats2half2_rn(f0.x, f0.y), h1 = __floats2half2_rn(f0.z, f0.w);
        __half2 h2 = __floats2half2_rn(f1.x, f1.y), h3 = __floats2half2_rn(f1.z, f1.w);
        uint4 u;
        u.x = *(uint32_t*)&h0; u.y = *(uint32_t*)&h1;
        u.z = *(uint32_t*)&h2; u.w = *(uint32_t*)&h3;
        *(uint4*)((char*)g_B[dir] + rr * 256 + cs_w * 16) = u;
    } else {
        const int cid = (b - 288) * 512 + tid;        // 36864
        const int kc = cid / 4096;
        const int rem = cid & 4095;
        const int n = rem >> 3, cs_w = rem & 7;
        const int chunk = cs_w ^ (n & 7);
        const int k0 = chunk * 8;
        float f[8];
#pragma unroll
        for (int i = 0; i < 8; ++i) {
            const int kk = kc * 64 + k0 + i;
            f[i] = (kk < KREAL) ? W_out[n * KREAL + kk] : 0.0f;
        }
        uint4 uh;
        __half2 p0 = __floats2half2_rn(f[0], f[1]), p1 = __floats2half2_rn(f[2], f[3]);
        __half2 p2 = __floats2half2_rn(f[4], f[5]), p3 = __floats2half2_rn(f[6], f[7]);
        uh.x = *(uint32_t*)&p0; uh.y = *(uint32_t*)&p1;
        uh.z = *(uint32_t*)&p2; uh.w = *(uint32_t*)&p3;
        *(uint4*)((char*)g_Wh + (uint32_t)(kc * 65536 + n * 128 + cs_w * 16)) = uh;
    }
}

// ---------------- HMMA bidirectional char-LSTM (R12-proven structure) ----------------
#define CI_OFF 0
#define A_OFF  4096
#define B_OFF  20480
#define P_OFF  151552
#define P_STRIDE 1072
#define LSTM_SMEM (P_OFF + 64 * P_STRIDE)   // 220160

__global__ __launch_bounds__(512, 1) void lstm_kernel(const int* __restrict__ char_ids) {
    extern __shared__ char smem[];
    const uint32_t sb = smem_u32(smem);
    int* ci_s = (int*)(smem + CI_OFF);

    const int tid = threadIdx.x, wid = tid >> 5, lane = tid & 31;
    const int dir = blockIdx.y;
    const int w_base = blockIdx.x * 64;
    const int wm = wid >> 3, wj = wid & 7;

    {
        const int* src = char_ids + (size_t)w_base * CL;
        ci_s[tid] = src[tid];
        ci_s[tid + 512] = src[tid + 512];
        float4* az = (float4*)(smem + A_OFF);
        az[tid] = make_float4(0.f, 0.f, 0.f, 0.f);
        az[tid + 512] = make_float4(0.f, 0.f, 0.f, 0.f);
        const float4* bsrc = (const float4*)g_B[dir];
        float4* bdst = (float4*)(smem + B_OFF);
#pragma unroll
        for (int i = 0; i < 16; ++i) bdst[tid + i * 512] = bsrc[tid + i * 512];
    }
    __syncthreads();

    const int pw = tid >> 3;
    const int pc0 = tid & 7;
    const uint32_t pdst0 = sb + P_OFF + pw * P_STRIDE;
    const char* psrc_dir = (const char*)g_P16 + ((size_t)dir << 17);

    {
        const int t0 = dir ? (CL - 1) : 0;
        const int ch = ci_s[pw * CL + t0];
        const char* srow = psrc_dir + ((size_t)ch << 10);
#pragma unroll
        for (int i = 0; i < 8; ++i) {
            const int c = pc0 + i * 8;
            cp16(pdst0 + c * 16, srow + c * 16);
        }
        cp_commit();
    }

    const int asub = lane >> 3;
    const int arow0 = wm * 32 + ((asub & 1) << 3) + (lane & 7);
    const int acp = asub >> 1;
    const int arm = arow0 & 7;
    const uint32_t a_base = sb + A_OFF + arow0 * 256;

    const int brow0 = wj * 64 + ((lane >> 4) << 3) + (lane & 7);
    const int bcp = (lane >> 3) & 1;
    const int brm = brow0 & 7;
    const uint32_t b_base = sb + B_OFF + brow0 * 256;

    const int mybar = 1 + wm;

    float d[2][8][4];
    float c_st[16], hs_st[16];
#pragma unroll
    for (int u = 0; u < 16; ++u) { c_st[u] = 0.f; hs_st[u] = 0.f; }

#pragma unroll 1
    for (int ti = 0; ti < CL; ++ti) {
        const int t = dir ? (CL - 1 - ti) : ti;

#pragma unroll
        for (int mt = 0; mt < 2; ++mt)
#pragma unroll
            for (int nt = 0; nt < 8; ++nt)
#pragma unroll
                for (int r = 0; r < 4; ++r) d[mt][nt][r] = 0.f;

        // gates = h(t-1) @ Whh^T
#pragma unroll
        for (int ks = 0; ks < 8; ++ks) {
            uint32_t A0[4], A1[4];
            ldm4(A0, a_base + (((ks * 2 + acp) ^ arm) << 4));
            ldm4(A1, a_base + 16 * 256 + (((ks * 2 + acp) ^ arm) << 4));
#pragma unroll
            for (int nb = 0; nb < 4; ++nb) {
                uint32_t B[4];
                ldm4(B, b_base + nb * 16 * 256 + (((ks * 2 + bcp) ^ brm) << 4));
                mma16816(d[0][nb * 2 + 0], A0, B[0], B[1]);
                mma16816(d[0][nb * 2 + 1], A0, B[2], B[3]);
                mma16816(d[1][nb * 2 + 0], A1, B[0], B[1]);
                mma16816(d[1][nb * 2 + 1], A1, B[2], B[3]);
            }
        }

        cp_wait0();
        bar_half(mybar);

        // epilogue: d += P(t), activations, c update, h sum, h(t) -> A
#pragma unroll
        for (int mt = 0; mt < 2; ++mt) {
#pragma unroll
            for (int rw = 0; rw < 2; ++rw) {
                const int wordl = wm * 32 + mt * 16 + (lane >> 2) + rw * 8;
#pragma unroll
                for (int jh = 0; jh < 2; ++jh) {
                    const int jg0 = wj * 16 + jh * 8 + 2 * (lane & 3);
                    uint32_t q[4];
                    lds128(q, sb + P_OFF + wordl * P_STRIDE + jg0 * 8);
                    float hv[2];
#pragma unroll
                    for (int rj = 0; rj < 2; ++rj) {
                        const float2 pa = __half22float2(*(__half2*)&q[rj * 2 + 0]);
                        const float2 pb = __half22float2(*(__half2*)&q[rj * 2 + 1]);
                        const int r = rw * 2 + rj;
                        const float gi = d[mt][0 + jh][r] + pa.x;
                        const float gf = d[mt][2 + jh][r] + pa.y;
                        const float gg = d[mt][4 + jh][r] + pb.x;
                        const float go = d[mt][6 + jh][r] + pb.y;
                        const int u = ((mt * 2 + rw) * 2 + jh) * 2 + rj;
                        const float cc = sig_m(gf) * c_st[u] + sig_m(gi) * tanh_m(gg);
                        c_st[u] = cc;
                        const float hh = sig_m(go) * tanh_m(cc);
                        hs_st[u] += hh;
                        hv[rj] = hh;
                    }
                    const int kk0 = wj * 16 + jh * 8 + 2 * (lane & 3);
                    const int chunk = kk0 >> 3;
                    const uint32_t off =
                        (uint32_t)(wordl * 256 + ((chunk ^ (wordl & 7)) << 4) + (kk0 & 7) * 2);
                    *(__half2*)(smem + A_OFF + off) = __floats2half2_rn(hv[0], hv[1]);
                }
            }
        }
        bar_half(mybar);

        // prefetch P(t+1)
        if (ti + 1 < CL) {
            const int tn = dir ? (t - 1) : (t + 1);
            const int ch = ci_s[pw * CL + tn];
            const char* srow = psrc_dir + ((size_t)ch << 10);
#pragma unroll
            for (int i = 0; i < 8; ++i) {
                const int c = pc0 + i * 8;
                cp16(pdst0 + c * 16, srow + c * 16);
            }
        }
        cp_commit();
    }

#pragma unroll
    for (int mt = 0; mt < 2; ++mt)
#pragma unroll
        for (int rw = 0; rw < 2; ++rw) {
            const int wordl = wm * 32 + mt * 16 + (lane >> 2) + rw * 8;
#pragma unroll
            for (int jh = 0; jh < 2; ++jh)
#pragma unroll
                for (int rj = 0; rj < 2; ++rj) {
                    const int jg = wj * 16 + jh * 8 + 2 * (lane & 3) + rj;
                    const int u = ((mt * 2 + rw) * 2 + jh) * 2 + rj;
                    g_cf[(size_t)(w_base + wordl) * 256 + dir * 128 + jg] = hs_st[u];
                }
        }
}

// ---------------- tensor-core output GEMM (single-pass fp16) ----------------
#define OG_WID 0
#define OG_AH  1024
#define OG_WH  9216
#define OG_SMEM (OG_WH + 65536)   // 74752

__global__ __launch_bounds__(512, 1) void outgemm_kernel(const int* __restrict__ word_ids,
                                                         const float* __restrict__ word_table,
                                                         const float* __restrict__ b_out,
                                                         float* __restrict__ out) {
    extern __shared__ char smem[];
    const uint32_t sb = smem_u32(smem);
    int* wid_s = (int*)(smem + OG_WID);

    const int tid = threadIdx.x, wid = tid >> 5, lane = tid & 31;
    const int w_base = blockIdx.x * 64;
    const int wm = wid >> 3, wn = wid & 7;

    if (tid < 64) wid_s[tid] = word_ids[w_base + tid];
    __syncthreads();

    const int asub = lane >> 3;
    const int arow0 = wm * 32 + ((asub & 1) << 3) + (lane & 7);
    const int acp = asub >> 1;
    const int arm = arow0 & 7;
    const uint32_t ah_base = sb + OG_AH + arow0 * 128;

    const int brow0 = wn * 64 + ((lane >> 4) << 3) + (lane & 7);
    const int bcp = (lane >> 3) & 1;
    const int brm = brow0 & 7;
    const uint32_t bh_base = sb + OG_WH + brow0 * 128;

    float d[2][8][4];
#pragma unroll
    for (int mt = 0; mt < 2; ++mt)
#pragma unroll
        for (int nt = 0; nt < 8; ++nt)
#pragma unroll
            for (int r = 0; r < 4; ++r) d[mt][nt][r] = 0.f;

    const int sm = tid >> 3;
    const int sk0 = (tid & 7) * 8;
    const int swid = wid_s[sm];
    const uint32_t soff = (uint32_t)(sm * 128 + (((sk0 >> 3) ^ (sm & 7)) << 4));

#pragma unroll 1
    for (int kc = 0; kc < 9; ++kc) {
        __syncthreads();
        {
            const char* srch = (const char*)g_Wh + kc * 65536;
#pragma unroll
            for (int i = 0; i < 8; ++i) {
                const uint32_t bo = (uint32_t)(tid + i * 512) * 16;
                cp16(sb + OG_WH + bo, srch + bo);
            }
            cp_commit();
        }
        {
            float f[8];
#pragma unroll
            for (int i = 0; i < 8; ++i) {
                const int kk = kc * 64 + sk0 + i;
                float v;
                if (kk < WDIM) v = word_table[(size_t)swid * WDIM + kk];
                else if (kk < KREAL) v = g_cf[(size_t)(w_base + sm) * 256 + (kk - WDIM)];
                else v = 0.0f;
                f[i] = v;
            }
            uint4 uh;
            __half2 p0 = __floats2half2_rn(f[0], f[1]), p1 = __floats2half2_rn(f[2], f[3]);
            __half2 p2 = __floats2half2_rn(f[4], f[5]), p3 = __floats2half2_rn(f[6], f[7]);
            uh.x = *(uint32_t*)&p0; uh.y = *(uint32_t*)&p1;
            uh.z = *(uint32_t*)&p2; uh.w = *(uint32_t*)&p3;
            *(uint4*)(smem + OG_AH + soff) = uh;
        }
        cp_wait0();
        __syncthreads();
#pragma unroll
        for (int ks = 0; ks < 4; ++ks) {
            const uint32_t aoff = (uint32_t)(((ks * 2 + acp) ^ arm) << 4);
            const uint32_t boff = (uint32_t)(((ks * 2 + bcp) ^ brm) << 4);
            uint32_t Ah0[4], Ah1[4];
            ldm4(Ah0, ah_base + aoff);
            ldm4(Ah1, ah_base + 16 * 128 + aoff);
#pragma unroll
            for (int nb = 0; nb < 4; ++nb) {
                uint32_t Bh[4];
                ldm4(Bh, bh_base + nb * 16 * 128 + boff);
                mma16816(d[0][nb * 2 + 0], Ah0, Bh[0], Bh[1]);
                mma16816(d[0][nb * 2 + 1], Ah0, Bh[2], Bh[3]);
                mma16816(d[1][nb * 2 + 0], Ah1, Bh[0], Bh[1]);
                mma16816(d[1][nb * 2 + 1], Ah1, Bh[2], Bh[3]);
            }
        }
    }

#pragma unroll
    for (int mt = 0; mt < 2; ++mt)
#pragma unroll
        for (int rw = 0; rw < 2; ++rw) {
            const int wordl = wm * 32 + mt * 16 + (lane >> 2) + rw * 8;
            const size_t row = (size_t)(w_base + wordl) * ODIM;
#pragma unroll
            for (int nt = 0; nt < 8; ++nt) {
                const int n0 = wn * 64 + nt * 8 + 2 * (lane & 3);
                float2 r;
                r.x = tanhf_fast(d[mt][nt][rw * 2 + 0] + b_out[n0]);
                r.y = tanhf_fast(d[mt][nt][rw * 2 + 1] + b_out[n0 + 1]);
                *(float2*)&out[row + n0] = r;
            }
        }
}

// ---------------- launch ----------------
extern "C" void kernel_launch(void* const* d_in, const int* in_sizes, int n_in,
                              void* d_out, int out_size) {
    const int* word_ids     = (const int*)d_in[0];
    const int* char_ids     = (const int*)d_in[1];
    const float* word_table = (const float*)d_in[2];
    const float* char_table = (const float*)d_in[3];
    const float* Wih_f = (const float*)d_in[4];
    const float* Whh_f = (const float*)d_in[5];
    const float* bih_f = (const float*)d_in[6];
    const float* bhh_f = (const float*)d_in[7];
    const float* Wih_b = (const float*)d_in[8];
    const float* Whh_b = (const float*)d_in[9];
    const float* bih_b = (const float*)d_in[10];
    const float* bhh_b = (const float*)d_in[11];
    const float* W_out = (const float*)d_in[12];
    const float* b_out = (const float*)d_in[13];
    float* out = (float*)d_out;

    cudaFuncSetAttribute(lstm_kernel, cudaFuncAttributeMaxDynamicSharedMemorySize, LSTM_SMEM);
    cudaFuncSetAttribute(outgemm_kernel, cudaFuncAttributeMaxDynamicSharedMemorySize, OG_SMEM);

    prep_all<<<360, 512>>>(char_table, Wih_f, bih_f, bhh_f, Wih_b, bih_b, bhh_b,
                           Whh_f, Whh_b, W_out);
    lstm_kernel<<<dim3(128, 2), 512, LSTM_SMEM>>>(char_ids);
    outgemm_kernel<<<128, 512, OG_SMEM>>>(word_ids, word_table, b_out, out);
}